// round 7
// baseline (speedup 1.0000x reference)
#include <cuda_runtime.h>
#include <cuda_bf16.h>
#include <math.h>

#define NN 8192
#define DD 256
#define KK 16
#define KSEL 17
#define MS 32            // screened survivors per row
#define BM 64
#define BN 128
#define JT (NN / BN)     // 64 j-tiles
#define QS 25.0f         // int8 quantization scale

__device__ float g_sq[NN];
__device__ __align__(16) int g_sqq[NN];
__device__ __align__(16) int g_fi8[NN * 64];      // packed int8 feats (64 ints/row)
__device__ unsigned long long g_cand[NN * MS];
__device__ unsigned long long g_best[NN * KSEL];

__device__ __forceinline__ unsigned smem_u32(const void* p) {
    unsigned a;
    asm("{ .reg .u64 t; cvta.to.shared.u64 t, %1; cvt.u32.u64 %0, t; }" : "=r"(a) : "l"(p));
    return a;
}
__device__ __forceinline__ unsigned mono(float f) {
    unsigned u = __float_as_uint(f);
    return (u & 0x80000000u) ? ~u : (u | 0x80000000u);
}

#define CP16(dst, src) asm volatile("cp.async.cg.shared.global [%0], [%1], 16;" :: "r"(dst), "l"(src) : "memory")
#define CP_COMMIT()    asm volatile("cp.async.commit_group;" ::: "memory")
#define CP_WAIT(n)     asm volatile("cp.async.wait_group %0;" :: "n"(n) : "memory")

__device__ __forceinline__ int q8f(float x) {
    int q = __float2int_rn(x * QS);
    return max(-127, min(127, q));
}
__device__ __forceinline__ unsigned pack4(float4 v) {
    int q0 = q8f(v.x), q1 = q8f(v.y), q2 = q8f(v.z), q3 = q8f(v.w);
    return (q0 & 0xff) | ((q1 & 0xff) << 8) | ((q2 & 0xff) << 16) | ((q3 & 0xff) << 24);
}

// ---------------- Kernel A: norms (fp32 + int) + int8 quantize ----------------
__global__ void sq_kernel(const float* __restrict__ feats) {
    int gw = (blockIdx.x * blockDim.x + threadIdx.x) >> 5;
    int lane = threadIdx.x & 31;
    if (gw >= NN) return;
    const float4* rowp = (const float4*)(feats + (size_t)gw * DD);
    float4 a = rowp[lane];
    float4 b = rowp[lane + 32];
    float s = a.x*a.x + a.y*a.y + a.z*a.z + a.w*a.w
            + b.x*b.x + b.y*b.y + b.z*b.z + b.w*b.w;
    int qa0 = q8f(a.x), qa1 = q8f(a.y), qa2 = q8f(a.z), qa3 = q8f(a.w);
    int qb0 = q8f(b.x), qb1 = q8f(b.y), qb2 = q8f(b.z), qb3 = q8f(b.w);
    int sq = qa0*qa0 + qa1*qa1 + qa2*qa2 + qa3*qa3
           + qb0*qb0 + qb1*qb1 + qb2*qb2 + qb3*qb3;
    #pragma unroll
    for (int o = 16; o; o >>= 1) {
        s  += __shfl_xor_sync(0xffffffffu, s, o);
        sq += __shfl_xor_sync(0xffffffffu, sq, o);
    }
    if (lane == 0) { g_sq[gw] = s; g_sqq[gw] = sq; }
    g_fi8[gw * 64 + lane]      = (int)pack4(a);
    g_fi8[gw * 64 + 32 + lane] = (int)pack4(b);
}

// ---------------- Kernel B: dp4a int8 GEMM screening -> approx top-32 per row ----------------
struct SmemK {
    int A[BM][68];                     // 17408 B (272B row stride)
    int B[2][BN][68];                  // 69632 B
    int sqB[2][BN];                    // 1024 B
    int thr[BM];
    int cnt[BM];
    unsigned long long best[BM][MS];   // 16384 B
    unsigned long long cand[BM][BN];   // 65536 B
};

__device__ __forceinline__ void prefetch_B(SmemK& sm, int s, int j0, int tid) {
    #pragma unroll
    for (int t = 0; t < 8; ++t) {
        int idx = t * 256 + tid;
        int r = idx >> 4, ch = idx & 15;
        unsigned dst = smem_u32(&sm.B[s][r][ch * 4]);
        const void* src = g_fi8 + (size_t)(j0 + r) * 64 + ch * 4;
        CP16(dst, src);
    }
    if (tid < 32) {
        unsigned dst = smem_u32(&sm.sqB[s][tid * 4]);
        const void* src = g_sqq + j0 + tid * 4;
        CP16(dst, src);
    }
}

__global__ void __launch_bounds__(256, 1) knn_kernel() {
    extern __shared__ char raw[];
    SmemK& sm = *reinterpret_cast<SmemK*>(raw);
    const int tid = threadIdx.x;
    const int tx = tid & 31;           // 0..31 -> cols tx + 32b
    const int ty = tid >> 5;           // 0..7  -> rows ty + 8a
    const int i0 = blockIdx.x * BM;

    // A tile prefetch (once): 64 rows x 256B = 1024 x 16B
    #pragma unroll
    for (int t = 0; t < 4; ++t) {
        int idx = t * 256 + tid;
        int r = idx >> 4, ch = idx & 15;
        unsigned dst = smem_u32(&sm.A[r][ch * 4]);
        const void* src = g_fi8 + (size_t)(i0 + r) * 64 + ch * 4;
        CP16(dst, src);
    }
    CP_COMMIT();
    prefetch_B(sm, 0, 0, tid);
    CP_COMMIT();

    if (tid < BM) {
        sm.thr[tid] = 0x7fffffff;
        sm.cnt[tid] = 0;
        #pragma unroll
        for (int t = 0; t < MS; ++t) sm.best[tid][t] = 0xFFFFFFFFFFFFFFFFull;
    }

    for (int jt = 0; jt < JT; ++jt) {
        const int s = jt & 1;
        const int j0 = jt * BN;

        if (jt + 1 < JT) {
            prefetch_B(sm, s ^ 1, (jt + 1) * BN, tid);
            CP_COMMIT();
            CP_WAIT(1);
        } else {
            CP_WAIT(0);
        }
        __syncthreads();   // B[s]+sqB[s] visible; prev flush (thr/best/cnt) visible

        // dp4a GEMM: 8x4 register tile per thread over K=64 ints
        int acc[8][4];
        #pragma unroll
        for (int a = 0; a < 8; ++a)
            #pragma unroll
            for (int b = 0; b < 4; ++b) acc[a][b] = 0;

        #pragma unroll 2
        for (int kc = 0; kc < 16; ++kc) {
            int4 aV[8], bV[4];
            #pragma unroll
            for (int a = 0; a < 8; ++a)
                aV[a] = *(const int4*)&sm.A[ty + 8 * a][kc * 4];     // warp-broadcast
            #pragma unroll
            for (int b = 0; b < 4; ++b)
                bV[b] = *(const int4*)&sm.B[s][tx + 32 * b][kc * 4]; // conflict-free
            #pragma unroll
            for (int a = 0; a < 8; ++a)
                #pragma unroll
                for (int b = 0; b < 4; ++b) {
                    acc[a][b] = __dp4a(aV[a].x, bV[b].x, acc[a][b]);
                    acc[a][b] = __dp4a(aV[a].y, bV[b].y, acc[a][b]);
                    acc[a][b] = __dp4a(aV[a].z, bV[b].z, acc[a][b]);
                    acc[a][b] = __dp4a(aV[a].w, bV[b].w, acc[a][b]);
                }
        }

        // scan: exact int32 rank key = sqq_j - 2*dot
        const int* sq = sm.sqB[s];
        int sqv[4];
        #pragma unroll
        for (int b = 0; b < 4; ++b) sqv[b] = sq[tx + 32 * b];
        #pragma unroll
        for (int a = 0; a < 8; ++a) {
            const int r = ty + 8 * a;
            const int t = sm.thr[r];
            #pragma unroll
            for (int b = 0; b < 4; ++b) {
                int v = sqv[b] - 2 * acc[a][b];
                if (v < t) {
                    int p = atomicAdd(&sm.cnt[r], 1);   // <= BN per row per tile
                    sm.cand[r][p] = ((unsigned long long)((unsigned)v ^ 0x80000000u) << 32)
                                  | (unsigned)(j0 + tx + 32 * b);
                }
            }
        }
        __syncthreads();

        // flush: one thread per row merges candidates into sorted top-32
        if (tid < BM) {
            int n = sm.cnt[tid];
            if (n) {
                sm.cnt[tid] = 0;
                unsigned long long* bl = sm.best[tid];
                for (int q = 0; q < n; ++q) {
                    unsigned long long key = sm.cand[tid][q];
                    if (key < bl[MS - 1]) {
                        int p = MS - 1;
                        while (p > 0 && bl[p - 1] > key) { bl[p] = bl[p - 1]; --p; }
                        bl[p] = key;
                    }
                }
                sm.thr[tid] = (int)((unsigned)(bl[MS - 1] >> 32) ^ 0x80000000u);
            }
        }
    }
    __syncthreads();

    for (int idx = tid; idx < BM * MS; idx += 256) {
        int r = idx / MS, t = idx % MS;
        g_cand[(size_t)(i0 + r) * MS + t] = sm.best[r][t];
    }
}

// ---------------- Kernel B2: exact fp32 refine of 32 survivors -> exact top-17 ----------------
__global__ void refine_kernel(const float* __restrict__ feats) {
    int row = (blockIdx.x * blockDim.x + threadIdx.x) >> 5;
    int lane = threadIdx.x & 31;
    if (row >= NN) return;

    const float* base = feats + (size_t)row * DD;
    float4 a0 = *(const float4*)(base + lane * 4);
    float4 a1 = *(const float4*)(base + 128 + lane * 4);
    float own[8] = {a0.x, a0.y, a0.z, a0.w, a1.x, a1.y, a1.z, a1.w};

    unsigned long long mykey = 0xFFFFFFFFFFFFFFFFull;

    #pragma unroll 4
    for (int t = 0; t < MS; ++t) {
        unsigned long long ak = g_cand[(size_t)row * MS + t];
        int j = (int)(unsigned)(ak & 0xffffffffull);
        const float* nb = feats + (size_t)j * DD;
        float4 b0 = *(const float4*)(nb + lane * 4);
        float4 b1 = *(const float4*)(nb + 128 + lane * 4);
        float p = own[0]*b0.x + own[1]*b0.y + own[2]*b0.z + own[3]*b0.w
                + own[4]*b1.x + own[5]*b1.y + own[6]*b1.z + own[7]*b1.w;
        #pragma unroll
        for (int o = 16; o; o >>= 1) p += __shfl_xor_sync(0xffffffffu, p, o);
        float val = fmaf(-2.f, p, g_sq[j]);
        if (lane == t)
            mykey = ((unsigned long long)mono(val) << 32) | (unsigned)j;
    }

    int rank = 0;
    #pragma unroll
    for (int s = 0; s < MS; ++s) {
        unsigned long long ok = __shfl_sync(0xffffffffu, mykey, s);
        rank += (ok < mykey);
    }
    if (rank < KSEL)
        g_best[(size_t)row * KSEL + rank] = mykey;
}

// ---------------- Kernel C: mutual mask + sparse softmax + AV + residual + normalize ----------------
__global__ void fuse_kernel(const float* __restrict__ feats, float* __restrict__ out) {
    int gw = (blockIdx.x * blockDim.x + threadIdx.x) >> 5;
    int lane = threadIdx.x & 31;
    if (gw >= NN) return;
    const int row = gw;
    const float* base = feats + (size_t)row * DD;
    float4 a0 = *(const float4*)(base + lane * 4);
    float4 a1 = *(const float4*)(base + 128 + lane * 4);
    float own[8] = {a0.x, a0.y, a0.z, a0.w, a1.x, a1.y, a1.z, a1.w};

    int my_nbr = -1;
    int cnt = 0;
    #pragma unroll
    for (int t = 0; t < KSEL; ++t) {
        unsigned long long key = g_best[(size_t)row * KSEL + t];
        int j = (int)(unsigned)(key & 0xffffffffull);
        if (j != row && cnt < KK) {
            if (cnt == lane) my_nbr = j;
            cnt++;
        }
    }

    bool found = false;
    if (lane < KK && my_nbr >= 0) {
        #pragma unroll
        for (int t = 0; t < KSEL; ++t) {
            unsigned long long key = g_best[(size_t)my_nbr * KSEL + t];
            if ((int)(unsigned)(key & 0xffffffffull) == row) found = true;
        }
    }
    unsigned mmask = __ballot_sync(0xffffffffu, found) & 0xffffu;

    float m = 1.0f, Z = 1.0f;
    float acc[8];
    #pragma unroll
    for (int e = 0; e < 8; ++e) acc[e] = own[e];

    for (int l = 0; l < KK; ++l) {
        if (!((mmask >> l) & 1u)) continue;
        int j = __shfl_sync(0xffffffffu, my_nbr, l);
        const float* nb = feats + (size_t)j * DD;
        float4 b0 = *(const float4*)(nb + lane * 4);
        float4 b1 = *(const float4*)(nb + 128 + lane * 4);
        float v[8] = {b0.x, b0.y, b0.z, b0.w, b1.x, b1.y, b1.z, b1.w};
        float p = 0.f;
        #pragma unroll
        for (int e = 0; e < 8; ++e) p = fmaf(own[e], v[e], p);
        #pragma unroll
        for (int o = 16; o; o >>= 1) p += __shfl_xor_sync(0xffffffffu, p, o);
        if (p > m) {
            float f = expf(m - p);
            Z = Z * f + 1.0f;
            #pragma unroll
            for (int e = 0; e < 8; ++e) acc[e] = fmaf(acc[e], f, v[e]);
            m = p;
        } else {
            float wgt = expf(p - m);
            Z += wgt;
            #pragma unroll
            for (int e = 0; e < 8; ++e) acc[e] = fmaf(wgt, v[e], acc[e]);
        }
    }

    float invZ = 1.0f / Z;
    float fcm[8];
    float ss = 0.f;
    #pragma unroll
    for (int e = 0; e < 8; ++e) {
        fcm[e] = fmaf(acc[e], invZ, own[e]);
        ss = fmaf(fcm[e], fcm[e], ss);
    }
    #pragma unroll
    for (int o = 16; o; o >>= 1) ss += __shfl_xor_sync(0xffffffffu, ss, o);
    float inv = 1.0f / fmaxf(sqrtf(ss), 1e-12f);

    float* op = out + (size_t)row * DD;
    *(float4*)(op + lane * 4)       = make_float4(fcm[0]*inv, fcm[1]*inv, fcm[2]*inv, fcm[3]*inv);
    *(float4*)(op + 128 + lane * 4) = make_float4(fcm[4]*inv, fcm[5]*inv, fcm[6]*inv, fcm[7]*inv);
}

// ---------------- launch ----------------
extern "C" void kernel_launch(void* const* d_in, const int* in_sizes, int n_in,
                              void* d_out, int out_size) {
    const float* feats = (const float*)d_in[0];
    float* out = (float*)d_out;
    (void)in_sizes; (void)n_in; (void)out_size;

    cudaFuncSetAttribute(knn_kernel, cudaFuncAttributeMaxDynamicSharedMemorySize,
                         (int)sizeof(SmemK));

    sq_kernel<<<NN / 8, 256>>>(feats);
    knn_kernel<<<NN / BM, 256, sizeof(SmemK)>>>();
    refine_kernel<<<NN / 8, 256>>>(feats);
    fuse_kernel<<<NN / 8, 256>>>(feats, out);
}

// round 8
// speedup vs baseline: 1.5354x; 1.5354x over previous
#include <cuda_runtime.h>
#include <cuda_fp16.h>
#include <math.h>

#define NN 8192
#define DD 256
#define KK 16
#define KSEL 17
#define MS 24            // screened survivors per row
#define BM 64
#define BN 64
#define JT (NN / BN)     // 128 j-tiles
#define RSB 264          // smem row stride in fp16 elements (528B)

__device__ float g_sq[NN];
__device__ __half2 g_fh16[NN * DD / 2];
__device__ unsigned long long g_cand[NN * MS];
__device__ unsigned long long g_best[NN * KSEL];

__device__ __forceinline__ unsigned smem_u32(const void* p) {
    unsigned a;
    asm("{ .reg .u64 t; cvta.to.shared.u64 t, %1; cvt.u32.u64 %0, t; }" : "=r"(a) : "l"(p));
    return a;
}
__device__ __forceinline__ unsigned mono(float f) {
    unsigned u = __float_as_uint(f);
    return (u & 0x80000000u) ? ~u : (u | 0x80000000u);
}
__device__ __forceinline__ float unmono(unsigned u) {
    return __uint_as_float((u & 0x80000000u) ? (u ^ 0x80000000u) : ~u);
}

#define CP16(dst, src) asm volatile("cp.async.cg.shared.global [%0], [%1], 16;" :: "r"(dst), "l"(src) : "memory")
#define CP_COMMIT()    asm volatile("cp.async.commit_group;" ::: "memory")
#define CP_WAIT(n)     asm volatile("cp.async.wait_group %0;" :: "n"(n) : "memory")
#define LDSM_X4(r0, r1, r2, r3, a) \
    asm volatile("ldmatrix.sync.aligned.m8n8.x4.shared.b16 {%0,%1,%2,%3}, [%4];" \
        : "=r"(r0), "=r"(r1), "=r"(r2), "=r"(r3) : "r"(a))
// f16 in / f16 accumulate: D,C are 2x .f16x2 registers
#define MMA_F16(d0, d1, a0, a1, a2, a3, b0, b1) \
    asm volatile("mma.sync.aligned.m16n8k16.row.col.f16.f16.f16.f16 " \
        "{%0,%1},{%2,%3,%4,%5},{%6,%7},{%0,%1};" \
        : "+r"(d0), "+r"(d1) \
        : "r"(a0), "r"(a1), "r"(a2), "r"(a3), "r"(b0), "r"(b1))

// ---------------- Kernel A: norms + fp16 convert ----------------
__global__ void sq_kernel(const float* __restrict__ feats) {
    int gw = (blockIdx.x * blockDim.x + threadIdx.x) >> 5;
    int lane = threadIdx.x & 31;
    if (gw >= NN) return;
    const float4* rowp = (const float4*)(feats + (size_t)gw * DD);
    float4 a = rowp[lane];
    float4 b = rowp[lane + 32];
    float s = a.x*a.x + a.y*a.y + a.z*a.z + a.w*a.w
            + b.x*b.x + b.y*b.y + b.z*b.z + b.w*b.w;
    #pragma unroll
    for (int o = 16; o; o >>= 1) s += __shfl_xor_sync(0xffffffffu, s, o);
    if (lane == 0) g_sq[gw] = s;
    __half2* dst = g_fh16 + (size_t)gw * (DD / 2);
    dst[lane * 2]          = __floats2half2_rn(a.x, a.y);
    dst[lane * 2 + 1]      = __floats2half2_rn(a.z, a.w);
    dst[64 + lane * 2]     = __floats2half2_rn(b.x, b.y);
    dst[64 + lane * 2 + 1] = __floats2half2_rn(b.z, b.w);
}

// ---------------- Kernel B: fp16 mma.sync screening -> approx top-24 per row ----------------
struct SmemK {
    __half A[BM][RSB];                 // 33792 B
    __half B[2][BN][RSB];              // 67584 B
    float sqB[2][BN];
    float thr[BM];
    int   cnt[BM];
    unsigned long long best[BM][MS];   // 12288 B
    unsigned long long cand[BM][BN];   // 32768 B
};

__device__ __forceinline__ void prefetch_B(SmemK& sm, int s, int j0, int tid) {
    #pragma unroll
    for (int t = 0; t < 8; ++t) {
        int idx = t * 256 + tid;
        int r = idx >> 5, ch = idx & 31;
        unsigned dst = smem_u32(&sm.B[s][r][ch * 8]);
        const void* src = (const char*)g_fh16 + (((size_t)(j0 + r) * DD) + ch * 8) * 2;
        CP16(dst, src);
    }
    if (tid < 16) {
        unsigned dst = smem_u32(&sm.sqB[s][tid * 4]);
        const void* src = g_sq + j0 + tid * 4;
        CP16(dst, src);
    }
}

__global__ void __launch_bounds__(256, 1) knn_kernel() {
    extern __shared__ char raw[];
    SmemK& sm = *reinterpret_cast<SmemK*>(raw);
    const int tid = threadIdx.x;
    const int lane = tid & 31;
    const int w = tid >> 5;
    const int wr = w >> 1;             // 0..3 -> 16-row strip
    const int wc = w & 1;              // 0..1 -> 32-col half
    const int i0 = blockIdx.x * BM;

    // A tile prefetch (once)
    #pragma unroll
    for (int t = 0; t < 8; ++t) {
        int idx = t * 256 + tid;
        int r = idx >> 5, ch = idx & 31;
        unsigned dst = smem_u32(&sm.A[r][ch * 8]);
        const void* src = (const char*)g_fh16 + (((size_t)(i0 + r) * DD) + ch * 8) * 2;
        CP16(dst, src);
    }
    CP_COMMIT();
    prefetch_B(sm, 0, 0, tid);
    CP_COMMIT();

    if (tid < BM) {
        sm.thr[tid] = __int_as_float(0x7f800000);
        sm.cnt[tid] = 0;
        #pragma unroll
        for (int t = 0; t < MS; ++t) sm.best[tid][t] = 0xFF800000FFFFFFFFull;
    }

    // ldmatrix source addresses
    const unsigned aAddr = smem_u32(&sm.A[wr * 16 + (lane & 15)][0]) + ((lane >> 4) << 4);
    const int rowB = wc * 32 + ((lane >> 4) << 3) + (lane & 7);
    const unsigned bColOff = ((lane >> 3) & 1) << 4;
    unsigned bAddrBase[2];
    bAddrBase[0] = smem_u32(&sm.B[0][rowB][0]) + bColOff;
    bAddrBase[1] = smem_u32(&sm.B[1][rowB][0]) + bColOff;

    const int R0 = wr * 16 + (lane >> 2);
    const int R1 = R0 + 8;
    const int cBase = wc * 32 + 2 * (lane & 3);

    for (int jt = 0; jt < JT; ++jt) {
        const int s = jt & 1;
        const int j0 = jt * BN;

        if (jt + 1 < JT) {
            prefetch_B(sm, s ^ 1, (jt + 1) * BN, tid);
            CP_COMMIT();
            CP_WAIT(1);
        } else {
            CP_WAIT(0);
        }
        __syncthreads();   // B[s]+sqB[s] visible; prev flush visible

        // MMA: warp tile 16x32 (4 n-tiles), 16 k-steps of k16, f16 accumulators
        unsigned acc[4][2];
        #pragma unroll
        for (int nt = 0; nt < 4; ++nt) { acc[nt][0] = 0u; acc[nt][1] = 0u; }

        const unsigned bA = bAddrBase[s];
        #pragma unroll
        for (int ks = 0; ks < 16; ++ks) {
            unsigned a0, a1, a2, a3;
            LDSM_X4(a0, a1, a2, a3, aAddr + ks * 32);
            unsigned p00, p01, p10, p11, q00, q01, q10, q11;
            LDSM_X4(p00, p01, p10, p11, bA + ks * 32);                  // n-tiles 0,1
            LDSM_X4(q00, q01, q10, q11, bA + 16 * (RSB * 2) + ks * 32); // n-tiles 2,3
            MMA_F16(acc[0][0], acc[0][1], a0, a1, a2, a3, p00, p01);
            MMA_F16(acc[1][0], acc[1][1], a0, a1, a2, a3, p10, p11);
            MMA_F16(acc[2][0], acc[2][1], a0, a1, a2, a3, q00, q01);
            MMA_F16(acc[3][0], acc[3][1], a0, a1, a2, a3, q10, q11);
        }

        // scan accumulators directly (convert f16x2 -> f32 pair)
        const float t0 = sm.thr[R0];
        const float t1 = sm.thr[R1];
        const float* sq = sm.sqB[s];
        #pragma unroll
        for (int nt = 0; nt < 4; ++nt) {
            const int c = cBase + nt * 8;
            float2 f0 = __half22float2(*(__half2*)&acc[nt][0]);   // row R0: cols c, c+1
            float2 f1 = __half22float2(*(__half2*)&acc[nt][1]);   // row R1: cols c, c+1
            float v00 = fmaf(-2.f, f0.x, sq[c]);
            float v01 = fmaf(-2.f, f0.y, sq[c + 1]);
            float v10 = fmaf(-2.f, f1.x, sq[c]);
            float v11 = fmaf(-2.f, f1.y, sq[c + 1]);
            if (v00 < t0) { int p = atomicAdd(&sm.cnt[R0], 1);
                sm.cand[R0][p] = ((unsigned long long)mono(v00) << 32) | (unsigned)(j0 + c); }
            if (v01 < t0) { int p = atomicAdd(&sm.cnt[R0], 1);
                sm.cand[R0][p] = ((unsigned long long)mono(v01) << 32) | (unsigned)(j0 + c + 1); }
            if (v10 < t1) { int p = atomicAdd(&sm.cnt[R1], 1);
                sm.cand[R1][p] = ((unsigned long long)mono(v10) << 32) | (unsigned)(j0 + c); }
            if (v11 < t1) { int p = atomicAdd(&sm.cnt[R1], 1);
                sm.cand[R1][p] = ((unsigned long long)mono(v11) << 32) | (unsigned)(j0 + c + 1); }
        }
        __syncthreads();

        // flush: one thread per row
        if (tid < BM) {
            int n = sm.cnt[tid];
            if (n) {
                sm.cnt[tid] = 0;
                unsigned long long* bl = sm.best[tid];
                for (int q = 0; q < n; ++q) {
                    unsigned long long key = sm.cand[tid][q];
                    if (key < bl[MS - 1]) {
                        int p = MS - 1;
                        while (p > 0 && bl[p - 1] > key) { bl[p] = bl[p - 1]; --p; }
                        bl[p] = key;
                    }
                }
                sm.thr[tid] = unmono((unsigned)(bl[MS - 1] >> 32));
            }
        }
    }
    __syncthreads();

    for (int idx = tid; idx < BM * MS; idx += 256) {
        int r = idx / MS, t = idx % MS;
        g_cand[(size_t)(i0 + r) * MS + t] = sm.best[r][t];
    }
}

// ---------------- Kernel B2: exact fp32 refine of 24 survivors -> exact top-17 ----------------
__global__ void refine_kernel(const float* __restrict__ feats) {
    int row = (blockIdx.x * blockDim.x + threadIdx.x) >> 5;
    int lane = threadIdx.x & 31;
    if (row >= NN) return;

    const float* base = feats + (size_t)row * DD;
    float4 a0 = *(const float4*)(base + lane * 4);
    float4 a1 = *(const float4*)(base + 128 + lane * 4);
    float own[8] = {a0.x, a0.y, a0.z, a0.w, a1.x, a1.y, a1.z, a1.w};

    unsigned long long mykey = 0xFFFFFFFFFFFFFFFFull;

    #pragma unroll 4
    for (int t = 0; t < MS; ++t) {
        unsigned long long ak = g_cand[(size_t)row * MS + t];
        int j = (int)(unsigned)(ak & 0xffffffffull);
        const float* nb = feats + (size_t)j * DD;
        float4 b0 = *(const float4*)(nb + lane * 4);
        float4 b1 = *(const float4*)(nb + 128 + lane * 4);
        float p = own[0]*b0.x + own[1]*b0.y + own[2]*b0.z + own[3]*b0.w
                + own[4]*b1.x + own[5]*b1.y + own[6]*b1.z + own[7]*b1.w;
        #pragma unroll
        for (int o = 16; o; o >>= 1) p += __shfl_xor_sync(0xffffffffu, p, o);
        float val = fmaf(-2.f, p, g_sq[j]);
        if (lane == t)
            mykey = ((unsigned long long)mono(val) << 32) | (unsigned)j;
    }

    int rank = 0;
    #pragma unroll
    for (int s = 0; s < MS; ++s) {
        unsigned long long ok = __shfl_sync(0xffffffffu, mykey, s);
        rank += (ok < mykey);
    }
    if (lane < MS && rank < KSEL)
        g_best[(size_t)row * KSEL + rank] = mykey;
}

// ---------------- Kernel C: mutual mask + sparse softmax + AV + residual + normalize ----------------
__global__ void fuse_kernel(const float* __restrict__ feats, float* __restrict__ out) {
    int gw = (blockIdx.x * blockDim.x + threadIdx.x) >> 5;
    int lane = threadIdx.x & 31;
    if (gw >= NN) return;
    const int row = gw;
    const float* base = feats + (size_t)row * DD;
    float4 a0 = *(const float4*)(base + lane * 4);
    float4 a1 = *(const float4*)(base + 128 + lane * 4);
    float own[8] = {a0.x, a0.y, a0.z, a0.w, a1.x, a1.y, a1.z, a1.w};

    int my_nbr = -1;
    int cnt = 0;
    #pragma unroll
    for (int t = 0; t < KSEL; ++t) {
        unsigned long long key = g_best[(size_t)row * KSEL + t];
        int j = (int)(unsigned)(key & 0xffffffffull);
        if (j != row && cnt < KK) {
            if (cnt == lane) my_nbr = j;
            cnt++;
        }
    }

    bool found = false;
    if (lane < KK && my_nbr >= 0) {
        #pragma unroll
        for (int t = 0; t < KSEL; ++t) {
            unsigned long long key = g_best[(size_t)my_nbr * KSEL + t];
            if ((int)(unsigned)(key & 0xffffffffull) == row) found = true;
        }
    }
    unsigned mmask = __ballot_sync(0xffffffffu, found) & 0xffffu;

    float m = 1.0f, Z = 1.0f;
    float acc[8];
    #pragma unroll
    for (int e = 0; e < 8; ++e) acc[e] = own[e];

    for (int l = 0; l < KK; ++l) {
        if (!((mmask >> l) & 1u)) continue;
        int j = __shfl_sync(0xffffffffu, my_nbr, l);
        const float* nb = feats + (size_t)j * DD;
        float4 b0 = *(const float4*)(nb + lane * 4);
        float4 b1 = *(const float4*)(nb + 128 + lane * 4);
        float v[8] = {b0.x, b0.y, b0.z, b0.w, b1.x, b1.y, b1.z, b1.w};
        float p = 0.f;
        #pragma unroll
        for (int e = 0; e < 8; ++e) p = fmaf(own[e], v[e], p);
        #pragma unroll
        for (int o = 16; o; o >>= 1) p += __shfl_xor_sync(0xffffffffu, p, o);
        if (p > m) {
            float f = expf(m - p);
            Z = Z * f + 1.0f;
            #pragma unroll
            for (int e = 0; e < 8; ++e) acc[e] = fmaf(acc[e], f, v[e]);
            m = p;
        } else {
            float wgt = expf(p - m);
            Z += wgt;
            #pragma unroll
            for (int e = 0; e < 8; ++e) acc[e] = fmaf(wgt, v[e], acc[e]);
        }
    }

    float invZ = 1.0f / Z;
    float fcm[8];
    float ss = 0.f;
    #pragma unroll
    for (int e = 0; e < 8; ++e) {
        fcm[e] = fmaf(acc[e], invZ, own[e]);
        ss = fmaf(fcm[e], fcm[e], ss);
    }
    #pragma unroll
    for (int o = 16; o; o >>= 1) ss += __shfl_xor_sync(0xffffffffu, ss, o);
    float inv = 1.0f / fmaxf(sqrtf(ss), 1e-12f);

    float* op = out + (size_t)row * DD;
    *(float4*)(op + lane * 4)       = make_float4(fcm[0]*inv, fcm[1]*inv, fcm[2]*inv, fcm[3]*inv);
    *(float4*)(op + 128 + lane * 4) = make_float4(fcm[4]*inv, fcm[5]*inv, fcm[6]*inv, fcm[7]*inv);
}

// ---------------- launch ----------------
extern "C" void kernel_launch(void* const* d_in, const int* in_sizes, int n_in,
                              void* d_out, int out_size) {
    const float* feats = (const float*)d_in[0];
    float* out = (float*)d_out;
    (void)in_sizes; (void)n_in; (void)out_size;

    cudaFuncSetAttribute(knn_kernel, cudaFuncAttributeMaxDynamicSharedMemorySize,
                         (int)sizeof(SmemK));

    sq_kernel<<<NN / 8, 256>>>(feats);
    knn_kernel<<<NN / BM, 256, sizeof(SmemK)>>>();
    refine_kernel<<<NN / 8, 256>>>(feats);
    fuse_kernel<<<NN / 8, 256>>>(feats, out);
}